// round 3
// baseline (speedup 1.0000x reference)
#include <cuda_runtime.h>
#include <cuda_fp16.h>

#define DIM 32
#define NODES_MAX 100000
#define EDGES_MAX 3200000
#define SCAN_BLK 1024
#define NB_MAX 128   // ceil(100000/1024)=98

// ---------------- scratch (device globals; no allocation allowed) ------------
__device__ __half g_p0[NODES_MAX * DIM];
__device__ __half g_p1[NODES_MAX * DIM];
__device__ int    g_deg[NODES_MAX];
__device__ int    g_row[NODES_MAX + 1];
__device__ int    g_wcur[NODES_MAX];
__device__ int    g_ssrc[EDGES_MAX];
__device__ int    g_bsum[NB_MAX];
__device__ int    g_bsum_ex[NB_MAX];
__device__ float  g_pool[DIM];

// ---------------- small init ------------------------------------------------
__global__ void k_zero(int n_nodes) {
    int stride = gridDim.x * blockDim.x;
    for (int i = blockIdx.x * blockDim.x + threadIdx.x; i < n_nodes; i += stride)
        g_deg[i] = 0;
    if (blockIdx.x == 0 && threadIdx.x < DIM) g_pool[threadIdx.x] = 0.0f;
}

// ---------------- CSR build (int4-vectorized) --------------------------------
__global__ void k_hist(const int* __restrict__ dst, int n_edges) {
    int stride = gridDim.x * blockDim.x;
    int n4 = n_edges >> 2;
    const int4* d4 = (const int4*)dst;
    for (int i = blockIdx.x * blockDim.x + threadIdx.x; i < n4; i += stride) {
        int4 v = __ldg(&d4[i]);
        atomicAdd(&g_deg[v.x], 1);
        atomicAdd(&g_deg[v.y], 1);
        atomicAdd(&g_deg[v.z], 1);
        atomicAdd(&g_deg[v.w], 1);
    }
    // tail
    int gid = blockIdx.x * blockDim.x + threadIdx.x;
    int base = n4 << 2;
    if (gid < (n_edges - base))
        atomicAdd(&g_deg[__ldg(&dst[base + gid])], 1);
}

__global__ void k_scan1(int n_nodes) {
    __shared__ int s[SCAN_BLK];
    int tid = threadIdx.x;
    int i = blockIdx.x * SCAN_BLK + tid;
    int v = (i < n_nodes) ? g_deg[i] : 0;
    s[tid] = v;
    __syncthreads();
    for (int off = 1; off < SCAN_BLK; off <<= 1) {
        int t = (tid >= off) ? s[tid - off] : 0;
        __syncthreads();
        s[tid] += t;
        __syncthreads();
    }
    if (i < n_nodes) g_row[i] = s[tid] - v;  // local exclusive
    if (tid == SCAN_BLK - 1) g_bsum[blockIdx.x] = s[tid];
}

__global__ void k_scan2(int nb) {
    __shared__ int s[NB_MAX];
    int tid = threadIdx.x;
    int v = (tid < nb) ? g_bsum[tid] : 0;
    s[tid] = v;
    __syncthreads();
    for (int off = 1; off < NB_MAX; off <<= 1) {
        int t = (tid >= off) ? s[tid - off] : 0;
        __syncthreads();
        s[tid] += t;
        __syncthreads();
    }
    g_bsum_ex[tid] = s[tid] - v;  // exclusive
}

__global__ void k_scan3(int n_nodes, int n_edges) {
    int stride = gridDim.x * blockDim.x;
    int gid = blockIdx.x * blockDim.x + threadIdx.x;
    for (int i = gid; i < n_nodes; i += stride) {
        int r = g_row[i] + g_bsum_ex[i / SCAN_BLK];
        g_row[i] = r;
        g_wcur[i] = r;
    }
    if (gid == 0) g_row[n_nodes] = n_edges;
}

__global__ void k_fill(const int* __restrict__ src, const int* __restrict__ dst,
                       int n_edges) {
    int stride = gridDim.x * blockDim.x;
    int n4 = n_edges >> 2;
    const int4* s4 = (const int4*)src;
    const int4* d4 = (const int4*)dst;
    for (int i = blockIdx.x * blockDim.x + threadIdx.x; i < n4; i += stride) {
        int4 d = __ldg(&d4[i]);
        int4 s = __ldg(&s4[i]);
        g_ssrc[atomicAdd(&g_wcur[d.x], 1)] = s.x;
        g_ssrc[atomicAdd(&g_wcur[d.y], 1)] = s.y;
        g_ssrc[atomicAdd(&g_wcur[d.z], 1)] = s.z;
        g_ssrc[atomicAdd(&g_wcur[d.w], 1)] = s.w;
    }
    int gid = blockIdx.x * blockDim.x + threadIdx.x;
    int base = n4 << 2;
    if (gid < (n_edges - base)) {
        int i = base + gid;
        g_ssrc[atomicAdd(&g_wcur[__ldg(&dst[i])], 1)] = __ldg(&src[i]);
    }
}

// ---------------- input projection: p0 = x @ w1a (half output) ---------------
// x row held in registers (3 slots, in_dim <= 96), broadcast via shfl.
__global__ void k_proj(const float* __restrict__ x, const float* __restrict__ w1a,
                       int n_nodes, int in_dim) {
    __shared__ float ws[96 * DIM];
    for (int i = threadIdx.x; i < in_dim * DIM; i += blockDim.x) ws[i] = w1a[i];
    __syncthreads();
    int lane = threadIdx.x & 31;
    int warp = (blockIdx.x * blockDim.x + threadIdx.x) >> 5;
    int nwarp = (gridDim.x * blockDim.x) >> 5;
    for (int n = warp; n < n_nodes; n += nwarp) {
        const float* xr = x + (size_t)n * in_dim;
        float xv0 = (lane < in_dim) ? __ldg(&xr[lane]) : 0.0f;
        float xv1 = (32 + lane < in_dim) ? __ldg(&xr[32 + lane]) : 0.0f;
        float xv2 = (64 + lane < in_dim) ? __ldg(&xr[64 + lane]) : 0.0f;
        float acc = 0.0f;
        int k = 0;
        for (; k < min(in_dim, 32); k++)
            acc = fmaf(__shfl_sync(0xffffffffu, xv0, k), ws[k * DIM + lane], acc);
        for (; k < min(in_dim, 64); k++)
            acc = fmaf(__shfl_sync(0xffffffffu, xv1, k - 32), ws[k * DIM + lane], acc);
        for (; k < in_dim; k++)
            acc = fmaf(__shfl_sync(0xffffffffu, xv2, k - 64), ws[k * DIM + lane], acc);
        g_p0[n * DIM + lane] = __float2half(acc);
    }
}

// ---------------- fused GIN layer (fp16 p, predicated 16-edge batches) -------
// Input:  p_in[n] = h_l[n] @ Wa_l  (half)
// Output: p_out[n] = relu(relu(segsum + self + Ba) @ Wb + Bb) @ Wa_next (half)
// If LAST: accumulate pooled sum of u = relu(...) into g_pool.
template <bool LAST>
__global__ void __launch_bounds__(256)
k_layer(const __half* __restrict__ p_in, __half* __restrict__ p_out,
        const float* __restrict__ Wb, const float* __restrict__ Bbv,
        const float* __restrict__ Bav, const float* __restrict__ Wanext,
        int n_nodes) {
    __shared__ float s_wb[DIM * DIM];
    __shared__ float s_wa[DIM * DIM];
    for (int i = threadIdx.x; i < DIM * DIM; i += blockDim.x) {
        s_wb[i] = Wb[i];
        if (!LAST) s_wa[i] = Wanext[i];
    }
    __syncthreads();

    const __half2* __restrict__ p2 = (const __half2*)p_in;
    int lane = threadIdx.x & 31;
    int half_id = lane >> 4;      // 0 or 1: which edge of the pair
    int fl = lane & 15;           // feature-pair index (features 2fl, 2fl+1)
    float ba_x = Bav[2 * fl], ba_y = Bav[2 * fl + 1];
    float bbv = Bbv[lane];

    int warp = (blockIdx.x * blockDim.x + threadIdx.x) >> 5;
    int nwarp = (gridDim.x * blockDim.x) >> 5;
    float pool = 0.0f;

    for (int n = warp; n < n_nodes; n += nwarp) {
        int beg = g_row[n];
        int end = g_row[n + 1];
        // self row: issue early so it's in flight with the first batch
        float2 sv = __half22float2(p2[n * 16 + fl]);

        float ax0 = 0.f, ay0 = 0.f, ax1 = 0.f, ay1 = 0.f;
        float ax2 = 0.f, ay2 = 0.f, ax3 = 0.f, ay3 = 0.f;
        float ax4 = 0.f, ay4 = 0.f, ax5 = 0.f, ay5 = 0.f;
        float ax6 = 0.f, ay6 = 0.f, ax7 = 0.f, ay7 = 0.f;

        // Predicated 16-edge batches: 8 independent idx loads + 8 predicated
        // gathers per batch. No serial remainder loop.
        for (int base = beg; base < end; base += 16) {
            int p0i = base + 0  + half_id, p1i = base + 2  + half_id;
            int p2i = base + 4  + half_id, p3i = base + 6  + half_id;
            int p4i = base + 8  + half_id, p5i = base + 10 + half_id;
            int p6i = base + 12 + half_id, p7i = base + 14 + half_id;
            int lim = end - 1;
            int s0 = __ldg(&g_ssrc[min(p0i, lim)]);
            int s1 = __ldg(&g_ssrc[min(p1i, lim)]);
            int s2 = __ldg(&g_ssrc[min(p2i, lim)]);
            int s3 = __ldg(&g_ssrc[min(p3i, lim)]);
            int s4 = __ldg(&g_ssrc[min(p4i, lim)]);
            int s5 = __ldg(&g_ssrc[min(p5i, lim)]);
            int s6 = __ldg(&g_ssrc[min(p6i, lim)]);
            int s7 = __ldg(&g_ssrc[min(p7i, lim)]);
            if (p0i < end) { float2 f = __half22float2(p2[s0 * 16 + fl]); ax0 += f.x; ay0 += f.y; }
            if (p1i < end) { float2 f = __half22float2(p2[s1 * 16 + fl]); ax1 += f.x; ay1 += f.y; }
            if (p2i < end) { float2 f = __half22float2(p2[s2 * 16 + fl]); ax2 += f.x; ay2 += f.y; }
            if (p3i < end) { float2 f = __half22float2(p2[s3 * 16 + fl]); ax3 += f.x; ay3 += f.y; }
            if (p4i < end) { float2 f = __half22float2(p2[s4 * 16 + fl]); ax4 += f.x; ay4 += f.y; }
            if (p5i < end) { float2 f = __half22float2(p2[s5 * 16 + fl]); ax5 += f.x; ay5 += f.y; }
            if (p6i < end) { float2 f = __half22float2(p2[s6 * 16 + fl]); ax6 += f.x; ay6 += f.y; }
            if (p7i < end) { float2 f = __half22float2(p2[s7 * 16 + fl]); ax7 += f.x; ay7 += f.y; }
        }

        float tx = ((ax0 + ax1) + (ax2 + ax3)) + ((ax4 + ax5) + (ax6 + ax7));
        float ty = ((ay0 + ay1) + (ay2 + ay3)) + ((ay4 + ay5) + (ay6 + ay7));
        // combine the two half-warps' partials
        tx += __shfl_xor_sync(0xffffffffu, tx, 16);
        ty += __shfl_xor_sync(0xffffffffu, ty, 16);
        // self term + bias + relu (consistent across both halves)
        tx = fmaxf(tx + sv.x + ba_x, 0.0f);
        ty = fmaxf(ty + sv.y + ba_y, 0.0f);

        // u_j = relu(sum_k t_k * Wb[k][j] + Bb[j]); j = lane
        float u = bbv;
#pragma unroll
        for (int k = 0; k < 16; k++) {
            float tkx = __shfl_sync(0xffffffffu, tx, k);
            float tky = __shfl_sync(0xffffffffu, ty, k);
            u = fmaf(tkx, s_wb[(2 * k) * DIM + lane], u);
            u = fmaf(tky, s_wb[(2 * k + 1) * DIM + lane], u);
        }
        u = fmaxf(u, 0.0f);

        if (!LAST) {
            float o = 0.0f;
#pragma unroll
            for (int k = 0; k < DIM; k++)
                o = fmaf(__shfl_sync(0xffffffffu, u, k), s_wa[k * DIM + lane], o);
            p_out[n * DIM + lane] = __float2half(o);
        } else {
            pool += u;
        }
    }

    if (LAST) {
        __shared__ float sp[8][DIM];
        int w = threadIdx.x >> 5;
        sp[w][lane] = pool;
        __syncthreads();
        if (w == 0) {
            float s = 0.0f;
#pragma unroll
            for (int i = 0; i < 8; i++) s += sp[i][lane];
            atomicAdd(&g_pool[lane], s);
        }
    }
}

// ---------------- head: out = relu(pool @ fc_w + fc_b) @ out_w + out_b -------
__global__ void k_head(const float* __restrict__ fcw, const float* __restrict__ fcb,
                       const float* __restrict__ outw, const float* __restrict__ outb,
                       float* __restrict__ out) {
    __shared__ float g2[DIM];
    int j = threadIdx.x;
    float acc = fcb[j];
    for (int k = 0; k < DIM; k++) acc = fmaf(g_pool[k], fcw[k * DIM + j], acc);
    g2[j] = fmaxf(acc, 0.0f);
    __syncwarp();
    float o = outb[j];
    for (int k = 0; k < DIM; k++) o = fmaf(g2[k], outw[k * DIM + j], o);
    out[j] = o;
}

// ---------------- launch ------------------------------------------------------
extern "C" void kernel_launch(void* const* d_in, const int* in_sizes, int n_in,
                              void* d_out, int out_size) {
    const float* x    = (const float*)d_in[0];
    const int*   ei   = (const int*)d_in[1];
    const float* w1a  = (const float*)d_in[2];
    const float* b1a  = (const float*)d_in[3];
    const float* w1b  = (const float*)d_in[4];
    const float* b1b  = (const float*)d_in[5];
    const float* wa   = (const float*)d_in[6];
    const float* ba   = (const float*)d_in[7];
    const float* wb   = (const float*)d_in[8];
    const float* bb   = (const float*)d_in[9];
    const float* fcw  = (const float*)d_in[10];
    const float* fcb  = (const float*)d_in[11];
    const float* outw = (const float*)d_in[12];
    const float* outb = (const float*)d_in[13];

    int in_dim  = in_sizes[2] / DIM;           // w1a is (in_dim, 32)
    int n_nodes = in_sizes[0] / in_dim;        // x is (n, in_dim)
    int n_edges = in_sizes[1] / 2;             // edge_index is (2, E)
    const int* src = ei;
    const int* dst = ei + n_edges;

    __half *p0, *p1;
    cudaGetSymbolAddress((void**)&p0, g_p0);
    cudaGetSymbolAddress((void**)&p1, g_p1);

    // CSR build + zero pool
    k_zero<<<256, 256>>>(n_nodes);
    k_hist<<<1024, 256>>>(dst, n_edges);
    int nb = (n_nodes + SCAN_BLK - 1) / SCAN_BLK;
    k_scan1<<<nb, SCAN_BLK>>>(n_nodes);
    k_scan2<<<1, NB_MAX>>>(nb);
    k_scan3<<<256, 256>>>(n_nodes, n_edges);
    k_fill<<<1024, 256>>>(src, dst, n_edges);

    // projection to first-layer pre-aggregation space
    k_proj<<<1024, 256>>>(x, w1a, n_nodes, in_dim);

    // 5 fused GIN layers (double-buffered p)
    k_layer<false><<<2048, 256>>>(p0, p1, w1b, b1b, b1a, wa + 0 * DIM * DIM, n_nodes);
    k_layer<false><<<2048, 256>>>(p1, p0, wb + 0 * DIM * DIM, bb + 0 * DIM, ba + 0 * DIM,
                                  wa + 1 * DIM * DIM, n_nodes);
    k_layer<false><<<2048, 256>>>(p0, p1, wb + 1 * DIM * DIM, bb + 1 * DIM, ba + 1 * DIM,
                                  wa + 2 * DIM * DIM, n_nodes);
    k_layer<false><<<2048, 256>>>(p1, p0, wb + 2 * DIM * DIM, bb + 2 * DIM, ba + 2 * DIM,
                                  wa + 3 * DIM * DIM, n_nodes);
    k_layer<true><<<2048, 256>>>(p0, nullptr, wb + 3 * DIM * DIM, bb + 3 * DIM,
                                 ba + 3 * DIM, nullptr, n_nodes);

    // graph head
    k_head<<<1, 32>>>(fcw, fcb, outw, outb, (float*)d_out);
}

// round 4
// speedup vs baseline: 1.1747x; 1.1747x over previous
#include <cuda_runtime.h>
#include <cuda_fp16.h>

#define DIM 32
#define NODES_MAX 100000
#define EDGES_MAX 3200000
#define SCAN_BLK 1024
#define NB_MAX 128   // ceil(100000/1024)=98

// ---------------- scratch (device globals; no allocation allowed) ------------
__device__ __half g_p0[NODES_MAX * DIM];
__device__ __half g_p1[NODES_MAX * DIM];
__device__ int    g_deg[NODES_MAX];
__device__ int    g_row[NODES_MAX + 1];
__device__ int    g_wcur[NODES_MAX];
__device__ int    g_ssrc[EDGES_MAX];
__device__ int    g_bsum[NB_MAX];
__device__ int    g_bsum_ex[NB_MAX];
__device__ float  g_pool[DIM];

// ---------------- small init ------------------------------------------------
__global__ void k_zero(int n_nodes) {
    int stride = gridDim.x * blockDim.x;
    for (int i = blockIdx.x * blockDim.x + threadIdx.x; i < n_nodes; i += stride)
        g_deg[i] = 0;
    if (blockIdx.x == 0 && threadIdx.x < DIM) g_pool[threadIdx.x] = 0.0f;
}

// ---------------- CSR build (scalar, R2 form) --------------------------------
__global__ void k_hist(const int* __restrict__ dst, int n_edges) {
    int stride = gridDim.x * blockDim.x;
    for (int i = blockIdx.x * blockDim.x + threadIdx.x; i < n_edges; i += stride)
        atomicAdd(&g_deg[__ldg(&dst[i])], 1);
}

__global__ void k_scan1(int n_nodes) {
    __shared__ int s[SCAN_BLK];
    int tid = threadIdx.x;
    int i = blockIdx.x * SCAN_BLK + tid;
    int v = (i < n_nodes) ? g_deg[i] : 0;
    s[tid] = v;
    __syncthreads();
    for (int off = 1; off < SCAN_BLK; off <<= 1) {
        int t = (tid >= off) ? s[tid - off] : 0;
        __syncthreads();
        s[tid] += t;
        __syncthreads();
    }
    if (i < n_nodes) g_row[i] = s[tid] - v;  // local exclusive
    if (tid == SCAN_BLK - 1) g_bsum[blockIdx.x] = s[tid];
}

__global__ void k_scan2(int nb) {
    __shared__ int s[NB_MAX];
    int tid = threadIdx.x;
    int v = (tid < nb) ? g_bsum[tid] : 0;
    s[tid] = v;
    __syncthreads();
    for (int off = 1; off < NB_MAX; off <<= 1) {
        int t = (tid >= off) ? s[tid - off] : 0;
        __syncthreads();
        s[tid] += t;
        __syncthreads();
    }
    g_bsum_ex[tid] = s[tid] - v;  // exclusive
}

__global__ void k_scan3(int n_nodes, int n_edges) {
    int stride = gridDim.x * blockDim.x;
    int gid = blockIdx.x * blockDim.x + threadIdx.x;
    for (int i = gid; i < n_nodes; i += stride) {
        int r = g_row[i] + g_bsum_ex[i / SCAN_BLK];
        g_row[i] = r;
        g_wcur[i] = r;
    }
    if (gid == 0) g_row[n_nodes] = n_edges;
}

__global__ void k_fill(const int* __restrict__ src, const int* __restrict__ dst,
                       int n_edges) {
    int stride = gridDim.x * blockDim.x;
    for (int i = blockIdx.x * blockDim.x + threadIdx.x; i < n_edges; i += stride) {
        int pos = atomicAdd(&g_wcur[__ldg(&dst[i])], 1);
        g_ssrc[pos] = __ldg(&src[i]);
    }
}

// ---------------- input projection: p0 = x @ w1a (half output) ---------------
__global__ void k_proj(const float* __restrict__ x, const float* __restrict__ w1a,
                       int n_nodes, int in_dim) {
    __shared__ float ws[96 * DIM];
    for (int i = threadIdx.x; i < in_dim * DIM; i += blockDim.x) ws[i] = w1a[i];
    __syncthreads();
    int lane = threadIdx.x & 31;
    int warp = (blockIdx.x * blockDim.x + threadIdx.x) >> 5;
    int nwarp = (gridDim.x * blockDim.x) >> 5;
    for (int n = warp; n < n_nodes; n += nwarp) {
        const float* xr = x + (size_t)n * in_dim;
        float xv0 = (lane < in_dim) ? __ldg(&xr[lane]) : 0.0f;
        float xv1 = (32 + lane < in_dim) ? __ldg(&xr[32 + lane]) : 0.0f;
        float xv2 = (64 + lane < in_dim) ? __ldg(&xr[64 + lane]) : 0.0f;
        float acc = 0.0f;
        int k = 0;
        for (; k < min(in_dim, 32); k++)
            acc = fmaf(__shfl_sync(0xffffffffu, xv0, k), ws[k * DIM + lane], acc);
        for (; k < min(in_dim, 64); k++)
            acc = fmaf(__shfl_sync(0xffffffffu, xv1, k - 32), ws[k * DIM + lane], acc);
        for (; k < in_dim; k++)
            acc = fmaf(__shfl_sync(0xffffffffu, xv2, k - 64), ws[k * DIM + lane], acc);
        g_p0[n * DIM + lane] = __float2half(acc);
    }
}

// ---------------- fused GIN layer: 4 edges per warp-load, mask arithmetic ----
// p rows are 64B fp16. Each lane loads uint2 (4 features); 8 lanes cover a row,
// so one warp-load gathers 4 source rows. A batch = 8 independent loads = 32 edges.
// Tail handled by index clamp + {0,1} multiplicative mask (branch-free).
template <bool LAST>
__global__ void __launch_bounds__(256)
k_layer(const __half* __restrict__ p_in, __half* __restrict__ p_out,
        const float* __restrict__ Wb, const float* __restrict__ Bbv,
        const float* __restrict__ Bav, const float* __restrict__ Wanext,
        int n_nodes) {
    __shared__ float s_wb[DIM * DIM];
    __shared__ float s_wa[DIM * DIM];
    for (int i = threadIdx.x; i < DIM * DIM; i += blockDim.x) {
        s_wb[i] = Wb[i];
        if (!LAST) s_wa[i] = Wanext[i];
    }
    __syncthreads();

    const uint2* __restrict__ pu = (const uint2*)p_in;  // row = 8 uint2
    int lane = threadIdx.x & 31;
    int quad = lane >> 3;    // which of 4 edges this lane serves in a load
    int fq   = lane & 7;     // feature-quad index: features 4fq .. 4fq+3
    float4 ba4 = __ldg(&((const float4*)Bav)[fq]);
    float bbv = Bbv[lane];

    int warp = (blockIdx.x * blockDim.x + threadIdx.x) >> 5;
    int nwarp = (gridDim.x * blockDim.x) >> 5;
    float pool = 0.0f;

    for (int n = warp; n < n_nodes; n += nwarp) {
        int beg = g_row[n];
        int end = g_row[n + 1];
        // self row in flight early
        uint2 svu = pu[n * 8 + fq];

        float a0x = 0.f, a0y = 0.f, a0z = 0.f, a0w = 0.f;
        float a1x = 0.f, a1y = 0.f, a1z = 0.f, a1w = 0.f;
        float a2x = 0.f, a2y = 0.f, a2z = 0.f, a2w = 0.f;
        float a3x = 0.f, a3y = 0.f, a3z = 0.f, a3w = 0.f;

        int lim = end - 1;
        for (int base = beg; base < end; base += 32) {
#define GATHER(J, AX, AY, AZ, AW)                                              \
            {                                                                  \
                int pos = base + 4 * (J) + quad;                               \
                int s = __ldg(&g_ssrc[min(pos, lim)]);                         \
                float m = (pos < end) ? 1.0f : 0.0f;                           \
                uint2 v = pu[s * 8 + fq];                                      \
                float2 lo = __half22float2(*(__half2*)&v.x);                   \
                float2 hi = __half22float2(*(__half2*)&v.y);                   \
                AX = fmaf(m, lo.x, AX); AY = fmaf(m, lo.y, AY);                \
                AZ = fmaf(m, hi.x, AZ); AW = fmaf(m, hi.y, AW);                \
            }
            GATHER(0, a0x, a0y, a0z, a0w)
            GATHER(1, a1x, a1y, a1z, a1w)
            GATHER(2, a2x, a2y, a2z, a2w)
            GATHER(3, a3x, a3y, a3z, a3w)
            GATHER(4, a0x, a0y, a0z, a0w)
            GATHER(5, a1x, a1y, a1z, a1w)
            GATHER(6, a2x, a2y, a2z, a2w)
            GATHER(7, a3x, a3y, a3z, a3w)
#undef GATHER
        }

        float t0 = (a0x + a1x) + (a2x + a3x);
        float t1 = (a0y + a1y) + (a2y + a3y);
        float t2 = (a0z + a1z) + (a2z + a3z);
        float t3 = (a0w + a1w) + (a2w + a3w);
        // combine the 4 quad partials: lanes {l, l^8, l^16, l^24} sum up
        t0 += __shfl_xor_sync(0xffffffffu, t0, 8);
        t1 += __shfl_xor_sync(0xffffffffu, t1, 8);
        t2 += __shfl_xor_sync(0xffffffffu, t2, 8);
        t3 += __shfl_xor_sync(0xffffffffu, t3, 8);
        t0 += __shfl_xor_sync(0xffffffffu, t0, 16);
        t1 += __shfl_xor_sync(0xffffffffu, t1, 16);
        t2 += __shfl_xor_sync(0xffffffffu, t2, 16);
        t3 += __shfl_xor_sync(0xffffffffu, t3, 16);

        // self + bias + relu
        float2 slo = __half22float2(*(__half2*)&svu.x);
        float2 shi = __half22float2(*(__half2*)&svu.y);
        t0 = fmaxf(t0 + slo.x + ba4.x, 0.0f);
        t1 = fmaxf(t1 + slo.y + ba4.y, 0.0f);
        t2 = fmaxf(t2 + shi.x + ba4.z, 0.0f);
        t3 = fmaxf(t3 + shi.y + ba4.w, 0.0f);

        // u_j = relu(sum_k t_k Wb[k][j] + Bb[j]); j = lane. t_{4f+r} lives in lane f.
        float u = bbv;
#pragma unroll
        for (int f = 0; f < 8; f++) {
            float c0 = __shfl_sync(0xffffffffu, t0, f);
            float c1 = __shfl_sync(0xffffffffu, t1, f);
            float c2 = __shfl_sync(0xffffffffu, t2, f);
            float c3 = __shfl_sync(0xffffffffu, t3, f);
            u = fmaf(c0, s_wb[(4 * f + 0) * DIM + lane], u);
            u = fmaf(c1, s_wb[(4 * f + 1) * DIM + lane], u);
            u = fmaf(c2, s_wb[(4 * f + 2) * DIM + lane], u);
            u = fmaf(c3, s_wb[(4 * f + 3) * DIM + lane], u);
        }
        u = fmaxf(u, 0.0f);

        if (!LAST) {
            float o = 0.0f;
#pragma unroll
            for (int k = 0; k < DIM; k++)
                o = fmaf(__shfl_sync(0xffffffffu, u, k), s_wa[k * DIM + lane], o);
            p_out[n * DIM + lane] = __float2half(o);
        } else {
            pool += u;
        }
    }

    if (LAST) {
        __shared__ float sp[8][DIM];
        int w = threadIdx.x >> 5;
        sp[w][lane] = pool;
        __syncthreads();
        if (w == 0) {
            float s = 0.0f;
#pragma unroll
            for (int i = 0; i < 8; i++) s += sp[i][lane];
            atomicAdd(&g_pool[lane], s);
        }
    }
}

// ---------------- head: out = relu(pool @ fc_w + fc_b) @ out_w + out_b -------
__global__ void k_head(const float* __restrict__ fcw, const float* __restrict__ fcb,
                       const float* __restrict__ outw, const float* __restrict__ outb,
                       float* __restrict__ out) {
    __shared__ float g2[DIM];
    int j = threadIdx.x;
    float acc = fcb[j];
    for (int k = 0; k < DIM; k++) acc = fmaf(g_pool[k], fcw[k * DIM + j], acc);
    g2[j] = fmaxf(acc, 0.0f);
    __syncwarp();
    float o = outb[j];
    for (int k = 0; k < DIM; k++) o = fmaf(g2[k], outw[k * DIM + j], o);
    out[j] = o;
}

// ---------------- launch ------------------------------------------------------
extern "C" void kernel_launch(void* const* d_in, const int* in_sizes, int n_in,
                              void* d_out, int out_size) {
    const float* x    = (const float*)d_in[0];
    const int*   ei   = (const int*)d_in[1];
    const float* w1a  = (const float*)d_in[2];
    const float* b1a  = (const float*)d_in[3];
    const float* w1b  = (const float*)d_in[4];
    const float* b1b  = (const float*)d_in[5];
    const float* wa   = (const float*)d_in[6];
    const float* ba   = (const float*)d_in[7];
    const float* wb   = (const float*)d_in[8];
    const float* bb   = (const float*)d_in[9];
    const float* fcw  = (const float*)d_in[10];
    const float* fcb  = (const float*)d_in[11];
    const float* outw = (const float*)d_in[12];
    const float* outb = (const float*)d_in[13];

    int in_dim  = in_sizes[2] / DIM;           // w1a is (in_dim, 32)
    int n_nodes = in_sizes[0] / in_dim;        // x is (n, in_dim)
    int n_edges = in_sizes[1] / 2;             // edge_index is (2, E)
    const int* src = ei;
    const int* dst = ei + n_edges;

    __half *p0, *p1;
    cudaGetSymbolAddress((void**)&p0, g_p0);
    cudaGetSymbolAddress((void**)&p1, g_p1);

    // CSR build + zero pool
    k_zero<<<256, 256>>>(n_nodes);
    k_hist<<<2048, 256>>>(dst, n_edges);
    int nb = (n_nodes + SCAN_BLK - 1) / SCAN_BLK;
    k_scan1<<<nb, SCAN_BLK>>>(n_nodes);
    k_scan2<<<1, NB_MAX>>>(nb);
    k_scan3<<<256, 256>>>(n_nodes, n_edges);
    k_fill<<<2048, 256>>>(src, dst, n_edges);

    // projection to first-layer pre-aggregation space
    k_proj<<<1024, 256>>>(x, w1a, n_nodes, in_dim);

    // 5 fused GIN layers (double-buffered p)
    k_layer<false><<<2048, 256>>>(p0, p1, w1b, b1b, b1a, wa + 0 * DIM * DIM, n_nodes);
    k_layer<false><<<2048, 256>>>(p1, p0, wb + 0 * DIM * DIM, bb + 0 * DIM, ba + 0 * DIM,
                                  wa + 1 * DIM * DIM, n_nodes);
    k_layer<false><<<2048, 256>>>(p0, p1, wb + 1 * DIM * DIM, bb + 1 * DIM, ba + 1 * DIM,
                                  wa + 2 * DIM * DIM, n_nodes);
    k_layer<false><<<2048, 256>>>(p1, p0, wb + 2 * DIM * DIM, bb + 2 * DIM, ba + 2 * DIM,
                                  wa + 3 * DIM * DIM, n_nodes);
    k_layer<true><<<2048, 256>>>(p0, nullptr, wb + 3 * DIM * DIM, bb + 3 * DIM,
                                 ba + 3 * DIM, nullptr, n_nodes);

    // graph head
    k_head<<<1, 32>>>(fcw, fcb, outw, outb, (float*)d_out);
}